// round 1
// baseline (speedup 1.0000x reference)
#include <cuda_runtime.h>

// Problem constants
#define D_MODEL 1024
#define S_LEN   2048
#define NH      16
#define HDIM    64
#define NBATCH  2
#define NTOK    (NBATCH * S_LEN)   // 4096

// Scratch (static __device__ globals — allocation-free per harness rules)
__device__ float g_Q [NTOK * D_MODEL];
__device__ float g_K [NTOK * D_MODEL];
__device__ float g_V [NTOK * D_MODEL];
__device__ float g_AO[NTOK * D_MODEL];

// ---------------------------------------------------------------------------
// GEMM: C[m][n] = sum_k A[m][k] * B[n][k] + bias[n]
// M = 4096, N = 1024, K = 1024 (fixed). Both A and B are K-contiguous.
// 128x128 block tile, k-tile 16, 256 threads, 8x8 microtile (split 4+4).
// ---------------------------------------------------------------------------
__global__ __launch_bounds__(256, 2)
void gemm_nt_bias(const float* __restrict__ A, const float* __restrict__ B,
                  const float* __restrict__ bias, float* __restrict__ C)
{
    __shared__ __align__(16) float As[16 * 132];
    __shared__ __align__(16) float Bs[16 * 132];

    const int tid = threadIdx.x;
    const int tx  = tid & 15;
    const int ty  = tid >> 4;
    const int bM  = blockIdx.y * 128;
    const int bN  = blockIdx.x * 128;

    float acc[8][8];
    #pragma unroll
    for (int i = 0; i < 8; i++)
        #pragma unroll
        for (int j = 0; j < 8; j++) acc[i][j] = 0.0f;

    for (int kt = 0; kt < D_MODEL; kt += 16) {
        // Load 128x16 tiles of A and B, transposed into smem [k][m].
        #pragma unroll
        for (int i = 0; i < 2; i++) {
            int j  = tid + i * 256;       // 0..511 float4 index
            int r  = j >> 2;              // row 0..127
            int c4 = j & 3;               // float4 col 0..3
            float4 va = *(const float4*)(A + (size_t)(bM + r) * D_MODEL + kt + c4 * 4);
            float4 vb = *(const float4*)(B + (size_t)(bN + r) * D_MODEL + kt + c4 * 4);
            int k0 = c4 * 4;
            As[(k0 + 0) * 132 + r] = va.x;
            As[(k0 + 1) * 132 + r] = va.y;
            As[(k0 + 2) * 132 + r] = va.z;
            As[(k0 + 3) * 132 + r] = va.w;
            Bs[(k0 + 0) * 132 + r] = vb.x;
            Bs[(k0 + 1) * 132 + r] = vb.y;
            Bs[(k0 + 2) * 132 + r] = vb.z;
            Bs[(k0 + 3) * 132 + r] = vb.w;
        }
        __syncthreads();

        #pragma unroll
        for (int k = 0; k < 16; k++) {
            float4 a0 = *(const float4*)&As[k * 132 + (ty << 2)];
            float4 a1 = *(const float4*)&As[k * 132 + 64 + (ty << 2)];
            float4 b0 = *(const float4*)&Bs[k * 132 + (tx << 2)];
            float4 b1 = *(const float4*)&Bs[k * 132 + 64 + (tx << 2)];
            float av[8] = {a0.x, a0.y, a0.z, a0.w, a1.x, a1.y, a1.z, a1.w};
            float bv[8] = {b0.x, b0.y, b0.z, b0.w, b1.x, b1.y, b1.z, b1.w};
            #pragma unroll
            for (int i = 0; i < 8; i++)
                #pragma unroll
                for (int j = 0; j < 8; j++)
                    acc[i][j] += av[i] * bv[j];
        }
        __syncthreads();
    }

    // Writeback with bias (vectorized, cols contiguous per float4)
    #pragma unroll
    for (int hr = 0; hr < 2; hr++) {
        #pragma unroll
        for (int a = 0; a < 4; a++) {
            int row = bM + hr * 64 + (ty << 2) + a;
            #pragma unroll
            for (int hc = 0; hc < 2; hc++) {
                int col = bN + hc * 64 + (tx << 2);
                float4 bb = *(const float4*)(bias + col);
                float4 o;
                o.x = acc[hr * 4 + a][hc * 4 + 0] + bb.x;
                o.y = acc[hr * 4 + a][hc * 4 + 1] + bb.y;
                o.z = acc[hr * 4 + a][hc * 4 + 2] + bb.z;
                o.w = acc[hr * 4 + a][hc * 4 + 3] + bb.w;
                *(float4*)(C + (size_t)row * D_MODEL + col) = o;
            }
        }
    }
}

// ---------------------------------------------------------------------------
// Causal flash attention, fp32.
// One block per (batch n, head h, 64-row query tile qb). 256 threads (16x16),
// 4x4 microtile of the 64x64 score tile per thread. Online softmax with
// shfl row-reductions. P tile reuses the K smem buffer. XOR swizzle keeps
// transposed smem traffic conflict-light. Static smem = exactly 48 KB.
// ---------------------------------------------------------------------------
#define SWZ(k, c) (((k) << 6) + ((c) ^ ((k) & 0x3C)))

__global__ __launch_bounds__(256)
void attn_kernel()
{
    __shared__ __align__(16) float Qs [64 * 64];  // [d][i]  (transposed, swizzled)
    __shared__ __align__(16) float KPs[64 * 64];  // [d][t] K, then [kk][i] P
    __shared__ __align__(16) float Vs [64 * 64];  // [kk][j] (natural)

    const int tid = threadIdx.x;
    const int tx  = tid & 15;
    const int ty  = tid >> 4;
    const int qb  = blockIdx.x;   // 0..31
    const int h   = blockIdx.y;   // 0..15
    const int n   = blockIdx.z;   // 0..1

    const size_t headbase = ((size_t)n * S_LEN) * D_MODEL + h * HDIM;
    const float* Qg = g_Q + headbase + (size_t)qb * 64 * D_MODEL;

    // Load Q tile transposed (once per block)
    #pragma unroll
    for (int i = 0; i < 4; i++) {
        int j  = tid + i * 256;     // 0..1023 float4 index
        int r  = j >> 4;            // query row 0..63
        int c4 = j & 15;            // float4 dim index
        float4 v = *(const float4*)(Qg + (size_t)r * D_MODEL + c4 * 4);
        int d = c4 * 4;
        Qs[SWZ(d + 0, r)] = v.x;
        Qs[SWZ(d + 1, r)] = v.y;
        Qs[SWZ(d + 2, r)] = v.z;
        Qs[SWZ(d + 3, r)] = v.w;
    }

    float m_i[4], l_i[4], acc[4][4];
    #pragma unroll
    for (int a = 0; a < 4; a++) {
        m_i[a] = -1e30f;
        l_i[a] = 0.0f;
        #pragma unroll
        for (int b = 0; b < 4; b++) acc[a][b] = 0.0f;
    }

    for (int kb = 0; kb <= qb; kb++) {
        __syncthreads();  // previous PV done reading KPs/Vs (also covers Qs fill)
        const float* Kg = g_K + headbase + (size_t)kb * 64 * D_MODEL;
        const float* Vg = g_V + headbase + (size_t)kb * 64 * D_MODEL;
        #pragma unroll
        for (int i = 0; i < 4; i++) {
            int j  = tid + i * 256;
            int r  = j >> 4;
            int c4 = j & 15;
            float4 kv = *(const float4*)(Kg + (size_t)r * D_MODEL + c4 * 4);
            float4 vv = *(const float4*)(Vg + (size_t)r * D_MODEL + c4 * 4);
            int d = c4 * 4;
            KPs[SWZ(d + 0, r)] = kv.x;
            KPs[SWZ(d + 1, r)] = kv.y;
            KPs[SWZ(d + 2, r)] = kv.z;
            KPs[SWZ(d + 3, r)] = kv.w;
            *(float4*)&Vs[r * 64 + c4 * 4] = vv;
        }
        __syncthreads();

        // S = Q K^T (64x64), 4x4 per thread, outer product over d
        float s[4][4];
        #pragma unroll
        for (int a = 0; a < 4; a++)
            #pragma unroll
            for (int b = 0; b < 4; b++) s[a][b] = 0.0f;

        #pragma unroll 8
        for (int k = 0; k < 64; k++) {
            float4 qa = *(const float4*)&Qs [SWZ(k, (ty << 2))];
            float4 kf = *(const float4*)&KPs[SWZ(k, (tx << 2))];
            float qv[4] = {qa.x, qa.y, qa.z, qa.w};
            float kv[4] = {kf.x, kf.y, kf.z, kf.w};
            #pragma unroll
            for (int a = 0; a < 4; a++)
                #pragma unroll
                for (int b = 0; b < 4; b++)
                    s[a][b] += qv[a] * kv[b];
        }

        // Scale + causal mask (only diagonal tile can mask)
        const bool diag = (kb == qb);
        #pragma unroll
        for (int a = 0; a < 4; a++) {
            int qi = (ty << 2) + a;
            #pragma unroll
            for (int b = 0; b < 4; b++) {
                int kj = (tx << 2) + b;
                float v = s[a][b] * 0.125f;   // 1/sqrt(64)
                if (diag && kj > qi) v = -1e30f;
                s[a][b] = v;
            }
        }

        // Online softmax (row stats live in registers of all 16 tx threads)
        #pragma unroll
        for (int a = 0; a < 4; a++) {
            float rm = fmaxf(fmaxf(s[a][0], s[a][1]), fmaxf(s[a][2], s[a][3]));
            #pragma unroll
            for (int o = 8; o > 0; o >>= 1)
                rm = fmaxf(rm, __shfl_xor_sync(0xFFFFFFFFu, rm, o));
            float mn   = fmaxf(m_i[a], rm);
            float corr = __expf(m_i[a] - mn);
            m_i[a] = mn;
            float rs = 0.0f;
            #pragma unroll
            for (int b = 0; b < 4; b++) {
                s[a][b] = __expf(s[a][b] - mn);
                rs += s[a][b];
            }
            #pragma unroll
            for (int o = 8; o > 0; o >>= 1)
                rs += __shfl_xor_sync(0xFFFFFFFFu, rs, o);
            l_i[a] = l_i[a] * corr + rs;
            #pragma unroll
            for (int b = 0; b < 4; b++) acc[a][b] *= corr;
        }

        __syncthreads();  // everyone done reading K from KPs
        // Write P transposed [kk][i] into the K buffer
        #pragma unroll
        for (int b = 0; b < 4; b++) {
            int kk = (tx << 2) + b;
            #pragma unroll
            for (int a = 0; a < 4; a++)
                KPs[SWZ(kk, (ty << 2) + a)] = s[a][b];
        }
        __syncthreads();

        // acc += P @ V
        #pragma unroll 8
        for (int kk = 0; kk < 64; kk++) {
            float4 pf = *(const float4*)&KPs[SWZ(kk, (ty << 2))];
            float4 vf = *(const float4*)&Vs [kk * 64 + (tx << 2)];
            float pv[4] = {pf.x, pf.y, pf.z, pf.w};
            float vv[4] = {vf.x, vf.y, vf.z, vf.w};
            #pragma unroll
            for (int a = 0; a < 4; a++)
                #pragma unroll
                for (int b = 0; b < 4; b++)
                    acc[a][b] += pv[a] * vv[b];
        }
    }

    // Epilogue: normalize and write attention output (token-major layout)
    float* Og = g_AO + headbase + (size_t)qb * 64 * D_MODEL;
    #pragma unroll
    for (int a = 0; a < 4; a++) {
        float inv = 1.0f / l_i[a];
        float4 o;
        o.x = acc[a][0] * inv;
        o.y = acc[a][1] * inv;
        o.z = acc[a][2] * inv;
        o.w = acc[a][3] * inv;
        *(float4*)(Og + (size_t)((ty << 2) + a) * D_MODEL + (tx << 2)) = o;
    }
}

// ---------------------------------------------------------------------------
// Launch
// ---------------------------------------------------------------------------
extern "C" void kernel_launch(void* const* d_in, const int* in_sizes, int n_in,
                              void* d_out, int out_size)
{
    const float* X  = (const float*)d_in[0];
    const float* Wq = (const float*)d_in[1];
    const float* bq = (const float*)d_in[2];
    const float* Wk = (const float*)d_in[3];
    const float* bk = (const float*)d_in[4];
    const float* Wv = (const float*)d_in[5];
    const float* bv = (const float*)d_in[6];
    const float* Wo = (const float*)d_in[7];
    const float* bo = (const float*)d_in[8];
    float* out = (float*)d_out;

    float *pQ, *pK, *pV, *pO;
    cudaGetSymbolAddress((void**)&pQ, g_Q);
    cudaGetSymbolAddress((void**)&pK, g_K);
    cudaGetSymbolAddress((void**)&pV, g_V);
    cudaGetSymbolAddress((void**)&pO, g_AO);

    dim3 gemm_grid(D_MODEL / 128, NTOK / 128);   // (8, 32)

    gemm_nt_bias<<<gemm_grid, 256>>>(X, Wq, bq, pQ);
    gemm_nt_bias<<<gemm_grid, 256>>>(X, Wk, bk, pK);
    gemm_nt_bias<<<gemm_grid, 256>>>(X, Wv, bv, pV);

    attn_kernel<<<dim3(S_LEN / 64, NH, NBATCH), 256>>>();

    gemm_nt_bias<<<gemm_grid, 256>>>(pO, Wo, bo, out);
}

// round 5
// speedup vs baseline: 1.5700x; 1.5700x over previous
#include <cuda_runtime.h>
#include <cstdint>

// Problem constants
#define D_MODEL 1024
#define S_LEN   2048
#define NH      16
#define HDIM    64
#define NBATCH  2
#define NTOK    (NBATCH * S_LEN)   // 4096

// Scratch (static __device__ globals — allocation-free per harness rules)
__device__ float g_Q [NTOK * D_MODEL];
__device__ float g_K [NTOK * D_MODEL];
__device__ float g_V [NTOK * D_MODEL];
__device__ float g_AO[NTOK * D_MODEL];

// ---------------------------------------------------------------------------
// Helpers
// ---------------------------------------------------------------------------
// tf32 cvt: destination MUST be a .b32 register ("=r"), not .f32.
__device__ __forceinline__ uint32_t f2tf32(float x) {
    uint32_t y; asm("cvt.rna.tf32.f32 %0, %1;" : "=r"(y) : "f"(x)); return y;
}
// Legacy tensor-core MMA (sm_80+): D[16x8] += A[16x8] * B[8x8], tf32 inputs.
__device__ __forceinline__ void mma_tf32(float* d, const uint32_t* a, const uint32_t* b) {
    asm volatile(
        "mma.sync.aligned.m16n8k8.row.col.f32.tf32.tf32.f32 "
        "{%0,%1,%2,%3}, {%4,%5,%6,%7}, {%8,%9}, {%0,%1,%2,%3};"
        : "+f"(d[0]), "+f"(d[1]), "+f"(d[2]), "+f"(d[3])
        : "r"(a[0]), "r"(a[1]), "r"(a[2]), "r"(a[3]), "r"(b[0]), "r"(b[1]));
}

// ===========================================================================
// Tensor-core tf32 GEMM: C[m][n] = sum_k A[m][k]*B[n][k] + bias[n]
// M=4096, N=1024, K=1024. 128x128 block tile, k-stage 32, double-buffered
// smem (one __syncthreads per stage), 8 warps (2x4), warp tile 64x32.
// Staged rows padded to 36 words -> fragment LDS is bank-conflict-free.
// ===========================================================================
#define ROWF 36                       // words per staged row (32 data + 4 pad)
#define STG_WORDS (128 * ROWF)        // one matrix, one buffer: 4608 words
#define GEMM_SMEM_BYTES (4 * STG_WORDS * 4)   // A0,B0,A1,B1 = 73728 B

__global__ __launch_bounds__(256, 1)
void gemm_mma_tf32(const float* __restrict__ A, const float* __restrict__ B,
                   const float* __restrict__ bias, float* __restrict__ C)
{
    extern __shared__ uint32_t sm[];
    const int tid  = threadIdx.x;
    const int lane = tid & 31;
    const int wid  = tid >> 5;
    const int g    = lane >> 2;       // group id (0..7)
    const int t    = lane & 3;        // thread-in-group (0..3)
    const int wm   = (wid >> 2) * 64; // warp m-base within tile
    const int wn   = (wid & 3) * 32;  // warp n-base within tile
    const int bM   = blockIdx.y * 128;
    const int bN   = blockIdx.x * 128;

    // Staging slots: 4 float4 of A + 4 of B per thread per 128x32 stage.
    const int c4 = tid & 7;           // float4 column within 32-word row
    const int r0 = tid >> 3;          // base row (rows r0, r0+32, r0+64, r0+96)
    const float* gA = A + (size_t)(bM + r0) * D_MODEL + c4 * 4;
    const float* gB = B + (size_t)(bN + r0) * D_MODEL + c4 * 4;
    const int so = r0 * ROWF + c4 * 4;          // smem word offset, row r0

    float acc[16][4];
    #pragma unroll
    for (int i = 0; i < 16; i++)
        #pragma unroll
        for (int j = 0; j < 4; j++) acc[i][j] = 0.0f;

    // ---- prologue: stage 0 into buffer 0 ----
    {
        uint32_t* dA = sm;
        uint32_t* dB = sm + STG_WORDS;
        #pragma unroll
        for (int i = 0; i < 4; i++) {
            float4 va = *(const float4*)(gA + (size_t)i * 32 * D_MODEL);
            float4 vb = *(const float4*)(gB + (size_t)i * 32 * D_MODEL);
            uint4 ca = {f2tf32(va.x), f2tf32(va.y), f2tf32(va.z), f2tf32(va.w)};
            uint4 cb = {f2tf32(vb.x), f2tf32(vb.y), f2tf32(vb.z), f2tf32(vb.w)};
            *(uint4*)(dA + so + i * 32 * ROWF) = ca;
            *(uint4*)(dB + so + i * 32 * ROWF) = cb;
        }
    }
    __syncthreads();

    for (int s = 0; s < 32; s++) {
        const uint32_t* bufA = sm + (s & 1) * 2 * STG_WORDS;
        const uint32_t* bufB = bufA + STG_WORDS;

        // Prefetch next stage into registers (hidden under the MMA work).
        float4 ra[4], rb[4];
        if (s + 1 < 32) {
            const int kt = (s + 1) * 32;
            #pragma unroll
            for (int i = 0; i < 4; i++) {
                ra[i] = *(const float4*)(gA + (size_t)i * 32 * D_MODEL + kt);
                rb[i] = *(const float4*)(gB + (size_t)i * 32 * D_MODEL + kt);
            }
        }

        // Compute: 4 k8-steps, 16 mma each.
        const uint32_t* pA = bufA + (wm + g) * ROWF + t;
        const uint32_t* pB = bufB + (wn + g) * ROWF + t;
        #pragma unroll
        for (int ks = 0; ks < 4; ks++) {
            const int k0 = ks * 8;
            uint32_t af[4][4], bf[4][2];
            #pragma unroll
            for (int i = 0; i < 4; i++) {
                af[i][0] = pA[(i * 16 + 0) * ROWF + k0];
                af[i][1] = pA[(i * 16 + 8) * ROWF + k0];
                af[i][2] = pA[(i * 16 + 0) * ROWF + k0 + 4];
                af[i][3] = pA[(i * 16 + 8) * ROWF + k0 + 4];
            }
            #pragma unroll
            for (int j = 0; j < 4; j++) {
                bf[j][0] = pB[j * 8 * ROWF + k0];
                bf[j][1] = pB[j * 8 * ROWF + k0 + 4];
            }
            #pragma unroll
            for (int i = 0; i < 4; i++)
                #pragma unroll
                for (int j = 0; j < 4; j++)
                    mma_tf32(acc[i * 4 + j], af[i], bf[j]);
        }

        // Store prefetched stage into the other buffer.
        if (s + 1 < 32) {
            uint32_t* dA = sm + ((s + 1) & 1) * 2 * STG_WORDS;
            uint32_t* dB = dA + STG_WORDS;
            #pragma unroll
            for (int i = 0; i < 4; i++) {
                uint4 ca = {f2tf32(ra[i].x), f2tf32(ra[i].y), f2tf32(ra[i].z), f2tf32(ra[i].w)};
                uint4 cb = {f2tf32(rb[i].x), f2tf32(rb[i].y), f2tf32(rb[i].z), f2tf32(rb[i].w)};
                *(uint4*)(dA + so + i * 32 * ROWF) = ca;
                *(uint4*)(dB + so + i * 32 * ROWF) = cb;
            }
        }
        __syncthreads();
    }

    // Epilogue: each C fragment -> two float2 stores with bias.
    #pragma unroll
    for (int i = 0; i < 4; i++) {
        const int m0 = bM + wm + i * 16 + g;
        #pragma unroll
        for (int j = 0; j < 4; j++) {
            const int col = bN + wn + j * 8 + 2 * t;
            float2 bb = *(const float2*)(bias + col);
            float2 v0 = {acc[i * 4 + j][0] + bb.x, acc[i * 4 + j][1] + bb.y};
            float2 v1 = {acc[i * 4 + j][2] + bb.x, acc[i * 4 + j][3] + bb.y};
            *(float2*)(C + (size_t)m0 * D_MODEL + col)       = v0;
            *(float2*)(C + (size_t)(m0 + 8) * D_MODEL + col) = v1;
        }
    }
}

// ---------------------------------------------------------------------------
// Causal flash attention, fp32 (unchanged — verified in round 1).
// ---------------------------------------------------------------------------
#define SWZ(k, c) (((k) << 6) + ((c) ^ ((k) & 0x3C)))

__global__ __launch_bounds__(256)
void attn_kernel()
{
    __shared__ __align__(16) float Qs [64 * 64];
    __shared__ __align__(16) float KPs[64 * 64];
    __shared__ __align__(16) float Vs [64 * 64];

    const int tid = threadIdx.x;
    const int tx  = tid & 15;
    const int ty  = tid >> 4;
    const int qb  = blockIdx.x;
    const int h   = blockIdx.y;
    const int n   = blockIdx.z;

    const size_t headbase = ((size_t)n * S_LEN) * D_MODEL + h * HDIM;
    const float* Qg = g_Q + headbase + (size_t)qb * 64 * D_MODEL;

    #pragma unroll
    for (int i = 0; i < 4; i++) {
        int j  = tid + i * 256;
        int r  = j >> 4;
        int c4 = j & 15;
        float4 v = *(const float4*)(Qg + (size_t)r * D_MODEL + c4 * 4);
        int d = c4 * 4;
        Qs[SWZ(d + 0, r)] = v.x;
        Qs[SWZ(d + 1, r)] = v.y;
        Qs[SWZ(d + 2, r)] = v.z;
        Qs[SWZ(d + 3, r)] = v.w;
    }

    float m_i[4], l_i[4], acc[4][4];
    #pragma unroll
    for (int a = 0; a < 4; a++) {
        m_i[a] = -1e30f;
        l_i[a] = 0.0f;
        #pragma unroll
        for (int b = 0; b < 4; b++) acc[a][b] = 0.0f;
    }

    for (int kb = 0; kb <= qb; kb++) {
        __syncthreads();
        const float* Kg = g_K + headbase + (size_t)kb * 64 * D_MODEL;
        const float* Vg = g_V + headbase + (size_t)kb * 64 * D_MODEL;
        #pragma unroll
        for (int i = 0; i < 4; i++) {
            int j  = tid + i * 256;
            int r  = j >> 4;
            int c4 = j & 15;
            float4 kv = *(const float4*)(Kg + (size_t)r * D_MODEL + c4 * 4);
            float4 vv = *(const float4*)(Vg + (size_t)r * D_MODEL + c4 * 4);
            int d = c4 * 4;
            KPs[SWZ(d + 0, r)] = kv.x;
            KPs[SWZ(d + 1, r)] = kv.y;
            KPs[SWZ(d + 2, r)] = kv.z;
            KPs[SWZ(d + 3, r)] = kv.w;
            *(float4*)&Vs[r * 64 + c4 * 4] = vv;
        }
        __syncthreads();

        float s[4][4];
        #pragma unroll
        for (int a = 0; a < 4; a++)
            #pragma unroll
            for (int b = 0; b < 4; b++) s[a][b] = 0.0f;

        #pragma unroll 8
        for (int k = 0; k < 64; k++) {
            float4 qa = *(const float4*)&Qs [SWZ(k, (ty << 2))];
            float4 kf = *(const float4*)&KPs[SWZ(k, (tx << 2))];
            float qv[4] = {qa.x, qa.y, qa.z, qa.w};
            float kv[4] = {kf.x, kf.y, kf.z, kf.w};
            #pragma unroll
            for (int a = 0; a < 4; a++)
                #pragma unroll
                for (int b = 0; b < 4; b++)
                    s[a][b] += qv[a] * kv[b];
        }

        const bool diag = (kb == qb);
        #pragma unroll
        for (int a = 0; a < 4; a++) {
            int qi = (ty << 2) + a;
            #pragma unroll
            for (int b = 0; b < 4; b++) {
                int kj = (tx << 2) + b;
                float v = s[a][b] * 0.125f;
                if (diag && kj > qi) v = -1e30f;
                s[a][b] = v;
            }
        }

        #pragma unroll
        for (int a = 0; a < 4; a++) {
            float rm = fmaxf(fmaxf(s[a][0], s[a][1]), fmaxf(s[a][2], s[a][3]));
            #pragma unroll
            for (int o = 8; o > 0; o >>= 1)
                rm = fmaxf(rm, __shfl_xor_sync(0xFFFFFFFFu, rm, o));
            float mn   = fmaxf(m_i[a], rm);
            float corr = __expf(m_i[a] - mn);
            m_i[a] = mn;
            float rs = 0.0f;
            #pragma unroll
            for (int b = 0; b < 4; b++) {
                s[a][b] = __expf(s[a][b] - mn);
                rs += s[a][b];
            }
            #pragma unroll
            for (int o = 8; o > 0; o >>= 1)
                rs += __shfl_xor_sync(0xFFFFFFFFu, rs, o);
            l_i[a] = l_i[a] * corr + rs;
            #pragma unroll
            for (int b = 0; b < 4; b++) acc[a][b] *= corr;
        }

        __syncthreads();
        #pragma unroll
        for (int b = 0; b < 4; b++) {
            int kk = (tx << 2) + b;
            #pragma unroll
            for (int a = 0; a < 4; a++)
                KPs[SWZ(kk, (ty << 2) + a)] = s[a][b];
        }
        __syncthreads();

        #pragma unroll 8
        for (int kk = 0; kk < 64; kk++) {
            float4 pf = *(const float4*)&KPs[SWZ(kk, (ty << 2))];
            float4 vf = *(const float4*)&Vs [kk * 64 + (tx << 2)];
            float pv[4] = {pf.x, pf.y, pf.z, pf.w};
            float vv[4] = {vf.x, vf.y, vf.z, vf.w};
            #pragma unroll
            for (int a = 0; a < 4; a++)
                #pragma unroll
                for (int b = 0; b < 4; b++)
                    acc[a][b] += pv[a] * vv[b];
        }
    }

    float* Og = g_AO + headbase + (size_t)qb * 64 * D_MODEL;
    #pragma unroll
    for (int a = 0; a < 4; a++) {
        float inv = 1.0f / l_i[a];
        float4 o;
        o.x = acc[a][0] * inv;
        o.y = acc[a][1] * inv;
        o.z = acc[a][2] * inv;
        o.w = acc[a][3] * inv;
        *(float4*)(Og + (size_t)((ty << 2) + a) * D_MODEL + (tx << 2)) = o;
    }
}

// ---------------------------------------------------------------------------
// Launch
// ---------------------------------------------------------------------------
extern "C" void kernel_launch(void* const* d_in, const int* in_sizes, int n_in,
                              void* d_out, int out_size)
{
    const float* X  = (const float*)d_in[0];
    const float* Wq = (const float*)d_in[1];
    const float* bq = (const float*)d_in[2];
    const float* Wk = (const float*)d_in[3];
    const float* bk = (const float*)d_in[4];
    const float* Wv = (const float*)d_in[5];
    const float* bv = (const float*)d_in[6];
    const float* Wo = (const float*)d_in[7];
    const float* bo = (const float*)d_in[8];
    float* out = (float*)d_out;

    float *pQ, *pK, *pV, *pO;
    cudaGetSymbolAddress((void**)&pQ, g_Q);
    cudaGetSymbolAddress((void**)&pK, g_K);
    cudaGetSymbolAddress((void**)&pV, g_V);
    cudaGetSymbolAddress((void**)&pO, g_AO);

    cudaFuncSetAttribute(gemm_mma_tf32, cudaFuncAttributeMaxDynamicSharedMemorySize,
                         GEMM_SMEM_BYTES);

    dim3 gemm_grid(D_MODEL / 128, NTOK / 128);   // (8, 32)

    gemm_mma_tf32<<<gemm_grid, 256, GEMM_SMEM_BYTES>>>(X, Wq, bq, pQ);
    gemm_mma_tf32<<<gemm_grid, 256, GEMM_SMEM_BYTES>>>(X, Wk, bk, pK);
    gemm_mma_tf32<<<gemm_grid, 256, GEMM_SMEM_BYTES>>>(X, Wv, bv, pV);

    attn_kernel<<<dim3(S_LEN / 64, NH, NBATCH), 256>>>();

    gemm_mma_tf32<<<gemm_grid, 256, GEMM_SMEM_BYTES>>>(pO, Wo, bo, out);
}

// round 6
// speedup vs baseline: 2.7110x; 1.7268x over previous
#include <cuda_runtime.h>
#include <cstdint>

// Problem constants
#define D_MODEL 1024
#define S_LEN   2048
#define NH      16
#define HDIM    64
#define NBATCH  2
#define NTOK    (NBATCH * S_LEN)   // 4096

// Scratch (static __device__ globals — allocation-free per harness rules)
__device__ float g_Q [NTOK * D_MODEL];
__device__ float g_K [NTOK * D_MODEL];
__device__ float g_V [NTOK * D_MODEL];
__device__ float g_AO[NTOK * D_MODEL];

// ---------------------------------------------------------------------------
// Helpers
// ---------------------------------------------------------------------------
// tf32 cvt: destination MUST be a .b32 register ("=r"), not .f32.
__device__ __forceinline__ uint32_t f2tf32(float x) {
    uint32_t y; asm("cvt.rna.tf32.f32 %0, %1;" : "=r"(y) : "f"(x)); return y;
}
// Legacy tensor-core MMA (sm_80+): D[16x8] += A[16x8] * B[8x8], tf32 inputs.
// Fragment layout verified on HW by the passing GEMM (R5).
__device__ __forceinline__ void mma_tf32(float* d, const uint32_t* a, const uint32_t* b) {
    asm volatile(
        "mma.sync.aligned.m16n8k8.row.col.f32.tf32.tf32.f32 "
        "{%0,%1,%2,%3}, {%4,%5,%6,%7}, {%8,%9}, {%0,%1,%2,%3};"
        : "+f"(d[0]), "+f"(d[1]), "+f"(d[2]), "+f"(d[3])
        : "r"(a[0]), "r"(a[1]), "r"(a[2]), "r"(a[3]), "r"(b[0]), "r"(b[1]));
}

// ===========================================================================
// Tensor-core tf32 GEMM (unchanged from R5 — verified).
// ===========================================================================
#define ROWF 36
#define STG_WORDS (128 * ROWF)
#define GEMM_SMEM_BYTES (4 * STG_WORDS * 4)   // 73728 B

__global__ __launch_bounds__(256, 1)
void gemm_mma_tf32(const float* __restrict__ A, const float* __restrict__ B,
                   const float* __restrict__ bias, float* __restrict__ C)
{
    extern __shared__ uint32_t sm[];
    const int tid  = threadIdx.x;
    const int lane = tid & 31;
    const int wid  = tid >> 5;
    const int g    = lane >> 2;
    const int t    = lane & 3;
    const int wm   = (wid >> 2) * 64;
    const int wn   = (wid & 3) * 32;
    const int bM   = blockIdx.y * 128;
    const int bN   = blockIdx.x * 128;

    const int c4 = tid & 7;
    const int r0 = tid >> 3;
    const float* gA = A + (size_t)(bM + r0) * D_MODEL + c4 * 4;
    const float* gB = B + (size_t)(bN + r0) * D_MODEL + c4 * 4;
    const int so = r0 * ROWF + c4 * 4;

    float acc[16][4];
    #pragma unroll
    for (int i = 0; i < 16; i++)
        #pragma unroll
        for (int j = 0; j < 4; j++) acc[i][j] = 0.0f;

    {
        uint32_t* dA = sm;
        uint32_t* dB = sm + STG_WORDS;
        #pragma unroll
        for (int i = 0; i < 4; i++) {
            float4 va = *(const float4*)(gA + (size_t)i * 32 * D_MODEL);
            float4 vb = *(const float4*)(gB + (size_t)i * 32 * D_MODEL);
            uint4 ca = {f2tf32(va.x), f2tf32(va.y), f2tf32(va.z), f2tf32(va.w)};
            uint4 cb = {f2tf32(vb.x), f2tf32(vb.y), f2tf32(vb.z), f2tf32(vb.w)};
            *(uint4*)(dA + so + i * 32 * ROWF) = ca;
            *(uint4*)(dB + so + i * 32 * ROWF) = cb;
        }
    }
    __syncthreads();

    for (int s = 0; s < 32; s++) {
        const uint32_t* bufA = sm + (s & 1) * 2 * STG_WORDS;
        const uint32_t* bufB = bufA + STG_WORDS;

        float4 ra[4], rb[4];
        if (s + 1 < 32) {
            const int kt = (s + 1) * 32;
            #pragma unroll
            for (int i = 0; i < 4; i++) {
                ra[i] = *(const float4*)(gA + (size_t)i * 32 * D_MODEL + kt);
                rb[i] = *(const float4*)(gB + (size_t)i * 32 * D_MODEL + kt);
            }
        }

        const uint32_t* pA = bufA + (wm + g) * ROWF + t;
        const uint32_t* pB = bufB + (wn + g) * ROWF + t;
        #pragma unroll
        for (int ks = 0; ks < 4; ks++) {
            const int k0 = ks * 8;
            uint32_t af[4][4], bf[4][2];
            #pragma unroll
            for (int i = 0; i < 4; i++) {
                af[i][0] = pA[(i * 16 + 0) * ROWF + k0];
                af[i][1] = pA[(i * 16 + 8) * ROWF + k0];
                af[i][2] = pA[(i * 16 + 0) * ROWF + k0 + 4];
                af[i][3] = pA[(i * 16 + 8) * ROWF + k0 + 4];
            }
            #pragma unroll
            for (int j = 0; j < 4; j++) {
                bf[j][0] = pB[j * 8 * ROWF + k0];
                bf[j][1] = pB[j * 8 * ROWF + k0 + 4];
            }
            #pragma unroll
            for (int i = 0; i < 4; i++)
                #pragma unroll
                for (int j = 0; j < 4; j++)
                    mma_tf32(acc[i * 4 + j], af[i], bf[j]);
        }

        if (s + 1 < 32) {
            uint32_t* dA = sm + ((s + 1) & 1) * 2 * STG_WORDS;
            uint32_t* dB = dA + STG_WORDS;
            #pragma unroll
            for (int i = 0; i < 4; i++) {
                uint4 ca = {f2tf32(ra[i].x), f2tf32(ra[i].y), f2tf32(ra[i].z), f2tf32(ra[i].w)};
                uint4 cb = {f2tf32(rb[i].x), f2tf32(rb[i].y), f2tf32(rb[i].z), f2tf32(rb[i].w)};
                *(uint4*)(dA + so + i * 32 * ROWF) = ca;
                *(uint4*)(dB + so + i * 32 * ROWF) = cb;
            }
        }
        __syncthreads();
    }

    #pragma unroll
    for (int i = 0; i < 4; i++) {
        const int m0 = bM + wm + i * 16 + g;
        #pragma unroll
        for (int j = 0; j < 4; j++) {
            const int col = bN + wn + j * 8 + 2 * t;
            float2 bb = *(const float2*)(bias + col);
            float2 v0 = {acc[i * 4 + j][0] + bb.x, acc[i * 4 + j][1] + bb.y};
            float2 v1 = {acc[i * 4 + j][2] + bb.x, acc[i * 4 + j][3] + bb.y};
            *(float2*)(C + (size_t)m0 * D_MODEL + col)       = v0;
            *(float2*)(C + (size_t)(m0 + 8) * D_MODEL + col) = v1;
        }
    }
}

// ===========================================================================
// Tensor-core causal flash attention (tf32 mma, fp32 softmax).
// One CTA per (n, h, 128-query tile). 8 warps; warp w owns rows [16w,16w+16)
// and the full 64-key / 64-d width, so softmax row stats reduce within a
// quad (2 shfls). Per 64-key tile: S-mma -> softmax -> P to smem -> PV-mma.
// K natural [key][d]; V transposed to [d][key] at load (conflict-free).
// Rows padded to 68 words => all fragment LDS bank-conflict-free.
// ===========================================================================
#define QT 128
#define KT 64
#define PAD 68
#define ATTN_SMEM_BYTES ((QT + KT + HDIM + QT) * PAD * 4)   // 104448 B

__global__ __launch_bounds__(256, 2)
void attn_mma()
{
    extern __shared__ uint32_t sma[];
    uint32_t* Qs = sma;                 // [128][68]  Q (pre-scaled, tf32)
    uint32_t* Ks = Qs + QT * PAD;       // [64][68]   K natural
    uint32_t* Vt = Ks + KT * PAD;       // [64][68]   V transposed [d][key]
    uint32_t* Ps = Vt + HDIM * PAD;     // [128][68]  P (tf32)

    const int tid  = threadIdx.x;
    const int lane = tid & 31;
    const int wid  = tid >> 5;
    const int g    = lane >> 2;
    const int t    = lane & 3;
    const int qt   = (int)(gridDim.x - 1) - (int)blockIdx.x;  // heavy tiles first
    const int h    = blockIdx.y;
    const int n    = blockIdx.z;
    const int qb0  = qt * QT;
    const int row0 = wid * 16;

    const size_t headbase = ((size_t)n * S_LEN) * D_MODEL + h * HDIM;

    // Load Q tile, pre-scaled by 1/sqrt(64), converted to tf32.
    {
        const float* Qg = g_Q + headbase + (size_t)qb0 * D_MODEL;
        #pragma unroll
        for (int i = 0; i < 8; i++) {
            int idx = tid + i * 256;      // 0..2047
            int r = idx >> 4, c4 = idx & 15;
            float4 v = *(const float4*)(Qg + (size_t)r * D_MODEL + c4 * 4);
            uint4 w = {f2tf32(v.x * 0.125f), f2tf32(v.y * 0.125f),
                       f2tf32(v.z * 0.125f), f2tf32(v.w * 0.125f)};
            *(uint4*)(Qs + r * PAD + c4 * 4) = w;
        }
    }

    float m_i[2] = {-1e30f, -1e30f};
    float l_i[2] = {0.0f, 0.0f};
    float acc[8][4];
    #pragma unroll
    for (int i = 0; i < 8; i++)
        #pragma unroll
        for (int j = 0; j < 4; j++) acc[i][j] = 0.0f;

    const int nkb = (qb0 + QT) / KT;     // 2*qt + 2 causal key tiles

    for (int kb = 0; kb < nkb; kb++) {
        __syncthreads();   // previous PV done reading Ks/Vt/Ps
        {
            const float* Kg = g_K + headbase + (size_t)kb * KT * D_MODEL;
            const float* Vg = g_V + headbase + (size_t)kb * KT * D_MODEL;
            #pragma unroll
            for (int i = 0; i < 4; i++) {
                int idx = tid + i * 256;          // 0..1023
                int r = idx >> 4, c4 = idx & 15;
                float4 kv = *(const float4*)(Kg + (size_t)r * D_MODEL + c4 * 4);
                uint4 kw = {f2tf32(kv.x), f2tf32(kv.y), f2tf32(kv.z), f2tf32(kv.w)};
                *(uint4*)(Ks + r * PAD + c4 * 4) = kw;
                // V transpose: warp reads 32 rows of one 16B column block,
                // stores scalars Vt[d][key] -> addr = const + lane (no conflicts)
                int rv = idx & 63, cv = idx >> 6; // cv 0..15
                float4 vv = *(const float4*)(Vg + (size_t)rv * D_MODEL + cv * 4);
                Vt[(cv * 4 + 0) * PAD + rv] = f2tf32(vv.x);
                Vt[(cv * 4 + 1) * PAD + rv] = f2tf32(vv.y);
                Vt[(cv * 4 + 2) * PAD + rv] = f2tf32(vv.z);
                Vt[(cv * 4 + 3) * PAD + rv] = f2tf32(vv.w);
            }
        }
        __syncthreads();

        // ---- S = (Q/8) K^T : 8 k-steps x 8 n-tiles of m16n8k8 ----
        float s[8][4];
        #pragma unroll
        for (int i = 0; i < 8; i++)
            #pragma unroll
            for (int j = 0; j < 4; j++) s[i][j] = 0.0f;

        #pragma unroll
        for (int ks = 0; ks < 8; ks++) {
            const uint32_t* pa = Qs + (row0 + g) * PAD + ks * 8 + t;
            uint32_t a[4] = {pa[0], pa[8 * PAD], pa[4], pa[8 * PAD + 4]};
            #pragma unroll
            for (int nt = 0; nt < 8; nt++) {
                const uint32_t* pb = Ks + (nt * 8 + g) * PAD + ks * 8 + t;
                uint32_t b[2] = {pb[0], pb[4]};
                mma_tf32(s[nt], a, b);
            }
        }

        // ---- causal mask (only near-diagonal tiles) ----
        const int r0g = qb0 + row0 + g;       // row of c0/c1
        if ((kb + 1) * KT - 1 > qb0 + row0) {
            #pragma unroll
            for (int nt = 0; nt < 8; nt++) {
                int c = kb * KT + nt * 8 + 2 * t;
                if (c     > r0g)     s[nt][0] = -1e30f;
                if (c + 1 > r0g)     s[nt][1] = -1e30f;
                if (c     > r0g + 8) s[nt][2] = -1e30f;
                if (c + 1 > r0g + 8) s[nt][3] = -1e30f;
            }
        }

        // ---- online softmax (rows g and g+8; quad reduction over t) ----
        float mx0 = -1e30f, mx1 = -1e30f;
        #pragma unroll
        for (int nt = 0; nt < 8; nt++) {
            mx0 = fmaxf(mx0, fmaxf(s[nt][0], s[nt][1]));
            mx1 = fmaxf(mx1, fmaxf(s[nt][2], s[nt][3]));
        }
        mx0 = fmaxf(mx0, __shfl_xor_sync(0xFFFFFFFFu, mx0, 1));
        mx0 = fmaxf(mx0, __shfl_xor_sync(0xFFFFFFFFu, mx0, 2));
        mx1 = fmaxf(mx1, __shfl_xor_sync(0xFFFFFFFFu, mx1, 1));
        mx1 = fmaxf(mx1, __shfl_xor_sync(0xFFFFFFFFu, mx1, 2));

        const float mn0 = fmaxf(m_i[0], mx0);
        const float mn1 = fmaxf(m_i[1], mx1);
        const float co0 = __expf(m_i[0] - mn0);
        const float co1 = __expf(m_i[1] - mn1);
        m_i[0] = mn0; m_i[1] = mn1;

        float rs0 = 0.0f, rs1 = 0.0f;
        #pragma unroll
        for (int nt = 0; nt < 8; nt++) {
            s[nt][0] = __expf(s[nt][0] - mn0);
            s[nt][1] = __expf(s[nt][1] - mn0);
            s[nt][2] = __expf(s[nt][2] - mn1);
            s[nt][3] = __expf(s[nt][3] - mn1);
            rs0 += s[nt][0] + s[nt][1];
            rs1 += s[nt][2] + s[nt][3];
        }
        rs0 += __shfl_xor_sync(0xFFFFFFFFu, rs0, 1);
        rs0 += __shfl_xor_sync(0xFFFFFFFFu, rs0, 2);
        rs1 += __shfl_xor_sync(0xFFFFFFFFu, rs1, 1);
        rs1 += __shfl_xor_sync(0xFFFFFFFFu, rs1, 2);
        l_i[0] = l_i[0] * co0 + rs0;
        l_i[1] = l_i[1] * co1 + rs1;

        #pragma unroll
        for (int nt = 0; nt < 8; nt++) {
            acc[nt][0] *= co0; acc[nt][1] *= co0;
            acc[nt][2] *= co1; acc[nt][3] *= co1;
        }

        // ---- write P (tf32) ----
        {
            uint32_t* p0 = Ps + (row0 + g) * PAD + 2 * t;
            uint32_t* p1 = p0 + 8 * PAD;
            #pragma unroll
            for (int nt = 0; nt < 8; nt++) {
                uint2 w0 = {f2tf32(s[nt][0]), f2tf32(s[nt][1])};
                uint2 w1 = {f2tf32(s[nt][2]), f2tf32(s[nt][3])};
                *(uint2*)(p0 + nt * 8) = w0;
                *(uint2*)(p1 + nt * 8) = w1;
            }
        }
        __syncthreads();

        // ---- acc += P V : 8 k-steps (keys) x 8 n-tiles (d) ----
        #pragma unroll
        for (int ks = 0; ks < 8; ks++) {
            const uint32_t* pa = Ps + (row0 + g) * PAD + ks * 8 + t;
            uint32_t a[4] = {pa[0], pa[8 * PAD], pa[4], pa[8 * PAD + 4]};
            #pragma unroll
            for (int nt = 0; nt < 8; nt++) {
                const uint32_t* pb = Vt + (nt * 8 + g) * PAD + ks * 8 + t;
                uint32_t b[2] = {pb[0], pb[4]};
                mma_tf32(acc[nt], a, b);
            }
        }
    }

    // ---- epilogue: normalize, write token-major attention output ----
    const float inv0 = 1.0f / l_i[0];
    const float inv1 = 1.0f / l_i[1];
    float* O0 = g_AO + headbase + (size_t)(qb0 + row0 + g) * D_MODEL;
    float* O1 = O0 + 8 * D_MODEL;
    #pragma unroll
    for (int nt = 0; nt < 8; nt++) {
        const int c = nt * 8 + 2 * t;
        float2 v0 = {acc[nt][0] * inv0, acc[nt][1] * inv0};
        float2 v1 = {acc[nt][2] * inv1, acc[nt][3] * inv1};
        *(float2*)(O0 + c) = v0;
        *(float2*)(O1 + c) = v1;
    }
}

// ---------------------------------------------------------------------------
// Launch
// ---------------------------------------------------------------------------
extern "C" void kernel_launch(void* const* d_in, const int* in_sizes, int n_in,
                              void* d_out, int out_size)
{
    const float* X  = (const float*)d_in[0];
    const float* Wq = (const float*)d_in[1];
    const float* bq = (const float*)d_in[2];
    const float* Wk = (const float*)d_in[3];
    const float* bk = (const float*)d_in[4];
    const float* Wv = (const float*)d_in[5];
    const float* bv = (const float*)d_in[6];
    const float* Wo = (const float*)d_in[7];
    const float* bo = (const float*)d_in[8];
    float* out = (float*)d_out;

    float *pQ, *pK, *pV, *pO;
    cudaGetSymbolAddress((void**)&pQ, g_Q);
    cudaGetSymbolAddress((void**)&pK, g_K);
    cudaGetSymbolAddress((void**)&pV, g_V);
    cudaGetSymbolAddress((void**)&pO, g_AO);

    cudaFuncSetAttribute(gemm_mma_tf32, cudaFuncAttributeMaxDynamicSharedMemorySize,
                         GEMM_SMEM_BYTES);
    cudaFuncSetAttribute(attn_mma, cudaFuncAttributeMaxDynamicSharedMemorySize,
                         ATTN_SMEM_BYTES);

    dim3 gemm_grid(D_MODEL / 128, NTOK / 128);   // (8, 32)

    gemm_mma_tf32<<<gemm_grid, 256, GEMM_SMEM_BYTES>>>(X, Wq, bq, pQ);
    gemm_mma_tf32<<<gemm_grid, 256, GEMM_SMEM_BYTES>>>(X, Wk, bk, pK);
    gemm_mma_tf32<<<gemm_grid, 256, GEMM_SMEM_BYTES>>>(X, Wv, bv, pV);

    attn_mma<<<dim3(S_LEN / QT, NH, NBATCH), 256, ATTN_SMEM_BYTES>>>();

    gemm_mma_tf32<<<gemm_grid, 256, GEMM_SMEM_BYTES>>>(pO, Wo, bo, out);
}